// round 9
// baseline (speedup 1.0000x reference)
#include <cuda_runtime.h>
#include <cuda_bf16.h>
#include <math.h>
#include <stdint.h>

// ---------------- problem constants ----------------
#define kB    16
#define kLIN  400
#define kT    100
#define kD    512
#define kH    8
#define kDep  64
#define kDFF  2048
#define kV    32000
#define kOOV  100
#define kVE   (kV + kOOV)   // 32100

#define ME (kB * kLIN)      // 6400
#define MD (kB * kT)        // 1600

// packed-weight sizes (uint2 units = 2 elements each)
#define SZ_DD   (kD * kD / 2)
#define SZ_DFF  (kD * kDFF / 2)
#define SZ_FW   (kD * kV / 2)
#define WP_TOTAL (16 * SZ_DD + 6 * SZ_DFF + SZ_FW)

// ---------------- scratch (device globals; no runtime alloc) ----------------
__device__ float g_pe [kLIN * kD];
__device__ float g_xe [ME * kD];
__device__ float g_q  [ME * kD];
__device__ float g_k  [ME * kD];
__device__ float g_v  [ME * kD];
__device__ float g_t  [ME * kD];
__device__ float g_cs [kB * kH * kT * kLIN];   // cross probs (block2)
__device__ float g_ffn[ME * kDFF];
__device__ float g_xd [MD * kD];
__device__ float g_emb[MD * kD];
__device__ float g_o1 [MD * kD];
__device__ float g_o2 [MD * kD];
__device__ float g_do [MD * kD];
__device__ float g_pg [MD];
__device__ float g_am [MD * kLIN];
__device__ uint2 g_wp [WP_TOTAL];
__device__ uint2 g_pa0[ME * kD / 2];
__device__ uint2 g_pa1[ME * kDFF / 2];
__device__ uint2 g_pa2[MD * kD / 2];

// ---------------- helpers ----------------
__device__ __forceinline__ float warp_sum(float v) {
    #pragma unroll
    for (int o = 16; o > 0; o >>= 1) v += __shfl_xor_sync(0xffffffffu, v, o);
    return v;
}
__device__ __forceinline__ float warp_max(float v) {
    #pragma unroll
    for (int o = 16; o > 0; o >>= 1) v = fmaxf(v, __shfl_xor_sync(0xffffffffu, v, o));
    return v;
}
__device__ __forceinline__ uint2 bfsplit2(float f0, float f1) {
    uint32_t hi;
    asm("cvt.rn.bf16x2.f32 %0, %1, %2;" : "=r"(hi) : "f"(f1), "f"(f0));
    __nv_bfloat162 h = *reinterpret_cast<__nv_bfloat162*>(&hi);
    float r0 = f0 - __bfloat162float(h.x);
    float r1 = f1 - __bfloat162float(h.y);
    uint32_t lo;
    asm("cvt.rn.bf16x2.f32 %0, %1, %2;" : "=r"(lo) : "f"(r1), "f"(r0));
    return make_uint2(hi, lo);
}
__device__ __forceinline__ void mma_bf16(float (&d)[4], const uint32_t (&a)[4], const uint32_t (&b)[2]) {
    asm volatile(
        "mma.sync.aligned.m16n8k16.row.col.f32.bf16.bf16.f32 "
        "{%0,%1,%2,%3},{%4,%5,%6,%7},{%8,%9},{%0,%1,%2,%3};"
        : "+f"(d[0]), "+f"(d[1]), "+f"(d[2]), "+f"(d[3])
        : "r"(a[0]), "r"(a[1]), "r"(a[2]), "r"(a[3]), "r"(b[0]), "r"(b[1]));
}

// ---------------- pack kernels ----------------
__global__ void pack_a_kernel(const float* __restrict__ in, uint2* __restrict__ out, int npairs) {
    int i = blockIdx.x * 256 + threadIdx.x;
    if (i >= npairs) return;
    float2 f = ((const float2*)in)[i];
    out[i] = bfsplit2(f.x, f.y);
}
__global__ void pack_b_kernel(const float* __restrict__ in, uint2* __restrict__ out, int Kp, int N) {
    int i = blockIdx.x * 256 + threadIdx.x;
    if (i >= Kp * N) return;
    int kp = i / N, n = i - kp * N;
    float f0 = in[(size_t)(2 * kp) * N + n];
    float f1 = in[(size_t)(2 * kp + 1) * N + n];
    out[i] = bfsplit2(f0, f1);
}

// ---------------- positional encoding ----------------
__global__ void pe_kernel(float* __restrict__ pe) {
    int i = blockIdx.x * 256 + threadIdx.x;
    if (i >= kLIN * kD) return;
    int pos = i / kD, d = i % kD;
    double rate = exp(-(double)(2 * (d / 2)) / (double)kD * log(10000.0));
    double ang  = (double)pos * rate;
    pe[i] = (float)((d & 1) ? cos(ang) : sin(ang));
}

// ---------------- embeddings ----------------
__global__ void embed_enc_kernel(const int* __restrict__ idx, const float* __restrict__ emb,
                                 const float* __restrict__ pe, float* __restrict__ x) {
    int t = blockIdx.x * 256 + threadIdx.x;
    if (t >= ME * kD) return;
    int d = t & (kD - 1);
    int bs = t >> 9;
    int s  = bs % kLIN;
    float scale = sqrtf((float)kD);
    x[t] = emb[(size_t)idx[bs] * kD + d] * scale + pe[s * kD + d];
}
__global__ void embed_dec_kernel(const int* __restrict__ idx, const float* __restrict__ emb,
                                 const float* __restrict__ pe, float* __restrict__ x,
                                 float* __restrict__ eraw) {
    int t = blockIdx.x * 256 + threadIdx.x;
    if (t >= MD * kD) return;
    int d = t & (kD - 1);
    int bs = t >> 9;
    int s  = bs % kT;
    float e = emb[(size_t)idx[bs] * kD + d];
    eraw[t] = e;
    float scale = sqrtf((float)kD);
    x[t] = e * scale + pe[s * kD + d];
}

// ---------------- bf16 3-term tensor-core GEMM, cp.async double buffered --------
// C[M,N] = A[M,K] @ W[K,N] + bias (+relu, +row-scale). Pre-packed hi/lo uint2.
// Tile 64(M) x 256(N), BK=32 (16 kpairs), 512 threads = 16 warps (2M x 8N),
// warp tile 32x32 via mma.m16n8k16. B: cp.async 2-stage; A: LDG->regs->STS.
// Requires M%64==0, N%256==0, K%32==0.
#define GEMM_SMEM_BYTES ((2*16*68 + 2*16*260) * 8)   // 83968
__global__ void __launch_bounds__(512)
gemm_bf16_kernel(const uint2* __restrict__ Ap, const uint2* __restrict__ Wp,
                 const float* __restrict__ bias, float* __restrict__ C,
                 int M, int N, int K, int ldc, int relu, const float* __restrict__ rs) {
    extern __shared__ uint2 sm[];
    uint2* Ab = sm;                 // 2 stages of [16][68]   (kpair-major, m)
    uint2* Bb = sm + 2 * 16 * 68;   // 2 stages of [16][260]  (kpair-major, n)

    const int t = threadIdx.x, lane = t & 31, wid = t >> 5;
    const int wm = wid & 1, wn = wid >> 1;          // 2 x 8 warp grid
    const int g = lane >> 2, c = lane & 3;
    const int bm = blockIdx.y << 6, bn = blockIdx.x << 8;
    const int Kp = K >> 1;
    const int nslab = Kp >> 4;

    const int am = t & 63, akq = (t >> 6) << 1;     // A: 1 uint4 (2 kpairs) per thread
    const uint2* aptr = Ap + (size_t)(bm + am) * Kp + akq;
    const int bkp = t >> 5, bj = (t & 31) << 1;     // B: 4 x 16B per thread
    const uint2* bptr = Wp + (size_t)bkp * N + bn + bj;

    uint4 av;
    float acc[2][4][4] = {};

    #define LDG_A(kp0)  av = *(const uint4*)(aptr + (kp0))
    #define STS_A(st) do { \
        uint2* a_ = Ab + (st) * (16 * 68); \
        a_[(akq    ) * 68 + am] = make_uint2(av.x, av.y); \
        a_[(akq + 1) * 68 + am] = make_uint2(av.z, av.w); \
    } while (0)
    #define CP_B(kp0, st) do { \
        uint2* brow_ = Bb + (st) * (16 * 260) + bkp * 260 + bj; \
        const uint2* grow_ = bptr + (size_t)(kp0) * N; \
        _Pragma("unroll") \
        for (int p_ = 0; p_ < 4; ++p_) { \
            uint32_t d_ = (uint32_t)__cvta_generic_to_shared(brow_ + 64 * p_); \
            asm volatile("cp.async.cg.shared.global [%0], [%1], 16;" \
                         :: "r"(d_), "l"(grow_ + 64 * p_)); \
        } \
        asm volatile("cp.async.commit_group;"); \
    } while (0)

    // prologue: stage 0
    LDG_A(0); STS_A(0); CP_B(0, 0);

    for (int sl = 0; sl < nslab; ++sl) {
        const int st = sl & 1;
        asm volatile("cp.async.wait_group 0;");
        __syncthreads();
        const bool pf = (sl + 1 < nslab);
        if (pf) { LDG_A((sl + 1) << 4); CP_B((sl + 1) << 4, st ^ 1); }

        const uint2 (*As)[68]  = (const uint2(*)[68]) (Ab + st * 16 * 68);
        const uint2 (*Bs)[260] = (const uint2(*)[260])(Bb + st * 16 * 260);
        #pragma unroll
        for (int s = 0; s < 2; ++s) {          // two k16 steps
            const int sb = s << 3;
            uint2 af[2][4], bf[4][2];
            #pragma unroll
            for (int mi = 0; mi < 2; ++mi) {
                int m = (wm << 5) + (mi << 4) + g;
                af[mi][0] = As[sb + c][m];
                af[mi][1] = As[sb + c][m + 8];
                af[mi][2] = As[sb + c + 4][m];
                af[mi][3] = As[sb + c + 4][m + 8];
            }
            #pragma unroll
            for (int ni = 0; ni < 4; ++ni) {
                int n = (wn << 5) + (ni << 3) + g;
                bf[ni][0] = Bs[sb + c][n];
                bf[ni][1] = Bs[sb + c + 4][n];
            }
            #pragma unroll
            for (int mi = 0; mi < 2; ++mi) {
                uint32_t ah[4] = {af[mi][0].x, af[mi][1].x, af[mi][2].x, af[mi][3].x};
                uint32_t al[4] = {af[mi][0].y, af[mi][1].y, af[mi][2].y, af[mi][3].y};
                #pragma unroll
                for (int ni = 0; ni < 4; ++ni) {
                    uint32_t bh[2] = {bf[ni][0].x, bf[ni][1].x};
                    uint32_t bl[2] = {bf[ni][0].y, bf[ni][1].y};
                    mma_bf16(acc[mi][ni], al, bh);
                    mma_bf16(acc[mi][ni], ah, bl);
                    mma_bf16(acc[mi][ni], ah, bh);
                }
            }
        }
        if (pf) STS_A(st ^ 1);
    }

    // ---- epilogue ----
    #pragma unroll
    for (int mi = 0; mi < 2; ++mi) {
        int r0 = bm + (wm << 5) + (mi << 4) + g;
        float s0 = rs ? rs[r0] : 1.0f;
        float s1 = rs ? rs[r0 + 8] : 1.0f;
        #pragma unroll
        for (int ni = 0; ni < 4; ++ni) {
            int c0 = bn + (wn << 5) + (ni << 3) + (c << 1);
            float bb0 = bias[c0], bb1 = bias[c0 + 1];
            float v0 = acc[mi][ni][0] + bb0, v1 = acc[mi][ni][1] + bb1;
            float v2 = acc[mi][ni][2] + bb0, v3 = acc[mi][ni][3] + bb1;
            if (relu) {
                v0 = fmaxf(v0, 0.0f); v1 = fmaxf(v1, 0.0f);
                v2 = fmaxf(v2, 0.0f); v3 = fmaxf(v3, 0.0f);
            }
            *(float2*)&C[(size_t)r0 * ldc + c0]       = make_float2(v0 * s0, v1 * s0);
            *(float2*)&C[(size_t)(r0 + 8) * ldc + c0] = make_float2(v2 * s1, v3 * s1);
        }
    }
}

// ---------------- fused attention: scores -> softmax (smem) -> P@V ----------------
#define ATTN_SMEM_BYTES ((32*408 + 32*68 + 32*68) * 4)
__global__ void __launch_bounds__(256)
fused_attn_kernel(const float* __restrict__ Q, const float* __restrict__ Kt,
                  const float* __restrict__ V, float* __restrict__ O,
                  int Sq, int Sk, const float* __restrict__ mask, int mode,
                  float* __restrict__ Pout) {
    extern __shared__ float sm_f[];
    float (*Ss)[408] = (float(*)[408])sm_f;
    float (*Qs)[68]  = (float(*)[68])(sm_f + 32 * 408);
    float (*Ks)[68]  = (float(*)[68])(sm_f + 32 * 408 + 32 * 68);

    const int tid = threadIdx.x;
    const int bh = blockIdx.y, b = bh >> 3, h = bh & 7;
    const int q0 = blockIdx.x * 32;

    for (int i = tid; i < 32 * 16; i += 256) {
        int r = i >> 4, c4 = (i & 15) << 2;
        float4 qv = make_float4(0, 0, 0, 0);
        if (q0 + r < Sq) qv = *(const float4*)&Q[((size_t)(b * Sq + q0 + r)) * kD + h * kDep + c4];
        *(float4*)&Qs[r][c4] = qv;
    }

    const int tx = tid & 15, ty = tid >> 4;
    for (int k0 = 0; k0 < Sk; k0 += 32) {
        for (int i = tid; i < 32 * 16; i += 256) {
            int r = i >> 4, c4 = (i & 15) << 2;
            float4 kv = make_float4(0, 0, 0, 0);
            if (k0 + r < Sk) kv = *(const float4*)&Kt[((size_t)(b * Sk + k0 + r)) * kD + h * kDep + c4];
            *(float4*)&Ks[r][c4] = kv;
        }
        __syncthreads();
        float acc[2][2] = {};
        #pragma unroll
        for (int d4 = 0; d4 < kDep; d4 += 4) {
            float4 a0 = *(const float4*)&Qs[ty * 2 + 0][d4];
            float4 a1 = *(const float4*)&Qs[ty * 2 + 1][d4];
            float4 b0 = *(const float4*)&Ks[tx * 2 + 0][d4];
            float4 b1 = *(const float4*)&Ks[tx * 2 + 1][d4];
            acc[0][0] += a0.x*b0.x + a0.y*b0.y + a0.z*b0.z + a0.w*b0.w;
            acc[0][1] += a0.x*b1.x + a0.y*b1.y + a0.z*b1.z + a0.w*b1.w;
            acc[1][0] += a1.x*b0.x + a1.y*b0.y + a1.z*b0.z + a1.w*b0.w;
            acc[1][1] += a1.x*b1.x + a1.y*b1.y + a1.z*b1.z + a1.w*b1.w;
        }
        #pragma unroll
        for (int i = 0; i < 2; ++i) {
            int qg = q0 + ty * 2 + i;
            #pragma unroll
            for (int j = 0; j < 2; ++j) {
                int kg = k0 + tx * 2 + j;
                if (qg < Sq && kg < Sk) {
                    float vv = acc[i][j] * 0.125f;
                    float mk = (mode == 0) ? mask[(size_t)b * Sk + kg]
                                           : mask[((size_t)b * Sq + qg) * Sk + kg];
                    Ss[ty * 2 + i][kg] = vv + mk * (-1e9f);
                }
            }
        }
        __syncthreads();
    }

    {
        const int wid = tid >> 5, lane = tid & 31;
        #pragma unroll
        for (int rr = 0; rr < 4; ++rr) {
            int r = (wid << 2) + rr;
            if (q0 + r < Sq) {
                float m = -1e30f;
                for (int i = lane; i < Sk; i += 32) m = fmaxf(m, Ss[r][i]);
                m = warp_max(m);
                float s = 0.0f;
                for (int i = lane; i < Sk; i += 32) { float e = __expf(Ss[r][i] - m); Ss[r][i] = e; s += e; }
                s = warp_sum(s);
                float inv = 1.0f / s;
                for (int i = lane; i < Sk; i += 32) Ss[r][i] *= inv;
            }
        }
    }
    __syncthreads();

    if (Pout) {
        for (int idx = tid; idx < 32 * Sk; idx += 256) {
            int r = idx / Sk, col = idx - r * Sk;
            if (q0 + r < Sq)
                Pout[((size_t)bh * Sq + q0 + r) * Sk + col] = Ss[r][col];
        }
    }

    const int dcol = tid & 63, qb = tid >> 6;
    float acc[8] = {};
    for (int k0 = 0; k0 < Sk; k0 += 32) {
        for (int i = tid; i < 32 * 16; i += 256) {
            int r = i >> 4, c4 = (i & 15) << 2;
            float4 v4 = make_float4(0, 0, 0, 0);
            if (k0 + r < Sk) v4 = *(const float4*)&V[((size_t)(b * Sk + k0 + r)) * kD + h * kDep + c4];
            *(float4*)&Ks[r][c4] = v4;
        }
        __syncthreads();
        int klim = Sk - k0; if (klim > 32) klim = 32;
        for (int kk = 0; kk < klim; ++kk) {
            float vv = Ks[kk][dcol];
            #pragma unroll
            for (int j = 0; j < 8; ++j)
                acc[j] = fmaf(Ss[qb + (j << 2)][k0 + kk], vv, acc[j]);
        }
        __syncthreads();
    }
    #pragma unroll
    for (int j = 0; j < 8; ++j) {
        int qg = q0 + qb + (j << 2);
        if (qg < Sq) O[((size_t)(b * Sq + qg)) * kD + h * kDep + dcol] = acc[j];
    }
}

// ---------------- context einsum: O = P @ V (per head) ----------------
__global__ void __launch_bounds__(256)
attn_out_kernel(const float* __restrict__ P, const float* __restrict__ V,
                float* __restrict__ O, int Sq, int Sk) {
    __shared__ float Ps[32][33];
    __shared__ float Vs[32][64];
    int tid = threadIdx.x;
    int bh = blockIdx.y, b = bh >> 3, h = bh & 7;
    int q0 = blockIdx.x * 32;
    const float* p = P + (size_t)bh * Sq * Sk;
    int dcol = tid & 63, qb = tid >> 6;
    float acc[8] = {};
    for (int k0 = 0; k0 < Sk; k0 += 32) {
        {
            int r = tid >> 3, cc = (tid & 7) << 2;
            int qg = q0 + r, kg = k0 + cc;
            float4 v4 = make_float4(0, 0, 0, 0);
            if (qg < Sq && kg < Sk)
                v4 = *(const float4*)&p[(size_t)qg * Sk + kg];
            Ps[r][cc] = v4.x; Ps[r][cc + 1] = v4.y; Ps[r][cc + 2] = v4.z; Ps[r][cc + 3] = v4.w;
        }
        for (int i = tid; i < 32 * 16; i += 256) {
            int r = i >> 4, c4 = (i & 15) << 2;
            int kg = k0 + r;
            float4 v4 = make_float4(0, 0, 0, 0);
            if (kg < Sk) v4 = *(const float4*)&V[((size_t)(b * Sk + kg)) * kD + h * kDep + c4];
            *(float4*)&Vs[r][c4] = v4;
        }
        __syncthreads();
        #pragma unroll
        for (int kk = 0; kk < 32; ++kk) {
            float vv = Vs[kk][dcol];
            #pragma unroll
            for (int j = 0; j < 8; ++j)
                acc[j] = fmaf(Ps[qb + (j << 2)][kk], vv, acc[j]);
        }
        __syncthreads();
    }
    #pragma unroll
    for (int j = 0; j < 8; ++j) {
        int qg = q0 + qb + (j << 2);
        if (qg < Sq) O[((size_t)(b * Sq + qg)) * kD + h * kDep + dcol] = acc[j];
    }
}

// ---------------- y = LN(x + a) * g + b ----------------
__global__ void add_ln_kernel(const float* __restrict__ x, const float* __restrict__ a,
                              float* __restrict__ y, const float* __restrict__ g,
                              const float* __restrict__ bb) {
    int row = blockIdx.x, tid = threadIdx.x;
    size_t base = (size_t)row * kD;
    float v[4], s = 0.0f, s2 = 0.0f;
    #pragma unroll
    for (int j = 0; j < 4; ++j) {
        int d = tid + j * 128;
        float t = x[base + d] + a[base + d];
        v[j] = t; s += t; s2 += t * t;
    }
    __shared__ float shs[4], shs2[4];
    s = warp_sum(s); s2 = warp_sum(s2);
    if ((tid & 31) == 0) { shs[tid >> 5] = s; shs2[tid >> 5] = s2; }
    __syncthreads();
    float S = shs[0] + shs[1] + shs[2] + shs[3];
    float S2 = shs2[0] + shs2[1] + shs2[2] + shs2[3];
    float mu = S * (1.0f / kD);
    float var = S2 * (1.0f / kD) - mu * mu;
    float rstd = rsqrtf(var + 1e-6f);
    #pragma unroll
    for (int j = 0; j < 4; ++j) {
        int d = tid + j * 128;
        y[base + d] = (v[j] - mu) * rstd * g[d] + bb[d];
    }
}

// ---------------- p_gen ----------------
__global__ void pgen_kernel(const float* __restrict__ ctx, const float* __restrict__ dec,
                            const float* __restrict__ emb, const float* __restrict__ w,
                            const float* __restrict__ bvec, float* __restrict__ pg) {
    int row = blockIdx.x, tid = threadIdx.x;
    float s = 0.0f;
    for (int d = tid; d < kD; d += 128) {
        size_t o = (size_t)row * kD + d;
        s += ctx[o] * w[d] + dec[o] * w[kD + d] + emb[o] * w[2 * kD + d];
    }
    __shared__ float sh[4];
    s = warp_sum(s);
    if ((tid & 31) == 0) sh[tid >> 5] = s;
    __syncthreads();
    if (tid == 0) {
        float t = sh[0] + sh[1] + sh[2] + sh[3] + bvec[0] + bvec[1] + bvec[2];
        pg[row] = 1.0f / (1.0f + expf(-t));
    }
}

// ---------------- attn_mean ----------------
__global__ void attn_mean_kernel(const float* __restrict__ P, float* __restrict__ am) {
    int i = blockIdx.x * 256 + threadIdx.x;
    if (i >= MD * kLIN) return;
    int l = i % kLIN;
    int bt = i / kLIN;
    int b = bt / kT, t = bt % kT;
    float s = 0.0f;
    #pragma unroll
    for (int h = 0; h < kH; ++h)
        s += P[(((size_t)(b * kH + h) * kT) + t) * kLIN + l];
    am[i] = s * (1.0f / kH);
}

// ---------------- zero extension columns ----------------
__global__ void zero_ext_kernel(float* __restrict__ out) {
    int i = blockIdx.x * 256 + threadIdx.x;
    if (i >= MD * kOOV) return;
    int row = i / kOOV, c = i % kOOV;
    out[(size_t)row * kVE + kV + c] = 0.0f;
}

// ---------------- copy scatter ----------------
__global__ void scatter_kernel(float* __restrict__ out, const float* __restrict__ am,
                               const float* __restrict__ pg, const int* __restrict__ ext) {
    int i = blockIdx.x * 256 + threadIdx.x;
    if (i >= MD * kLIN) return;
    int l = i % kLIN;
    int bt = i / kLIN;
    int b = bt / kT;
    float v = (1.0f - pg[bt]) * am[i];
    int vi = ext[b * kLIN + l];
    atomicAdd(&out[(size_t)bt * kVE + vi], v);
}

// ---------------- host orchestration ----------------
extern "C" void kernel_launch(void* const* d_in, const int* in_sizes, int n_in,
                              void* d_out, int out_size) {
    int off = (n_in > 6 && in_sizes[6] == 1) ? 1 : 0;
    const int*   inp      = (const int*)d_in[0];
    const int*   tar      = (const int*)d_in[1];
    const int*   ext      = (const int*)d_in[2];
    const float* enc_mask = (const float*)d_in[3];
    const float* la_mask  = (const float*)d_in[4];
    const float* dec_mask = (const float*)d_in[5];
    const float* emb_enc  = (const float*)d_in[6 + off];
    const float* emb_dec  = (const float*)d_in[7 + off];
    const float* eaw = (const float*)d_in[8 + off];
    const float* eab = (const float*)d_in[9 + off];
    const float* ew1 = (const float*)d_in[10 + off];
    const float* eb1 = (const float*)d_in[11 + off];
    const float* ew2 = (const float*)d_in[12 + off];
    const float* eb2 = (const float*)d_in[13 + off];
    const float* elg = (const float*)d_in[14 + off];
    const float* elb = (const float*)d_in[15 + off];
    const float* daw = (const float*)d_in[16 + off];
    const float* dab = (const float*)d_in[17 + off];
    const float* dw1 = (const float*)d_in[18 + off];
    const float* db1 = (const float*)d_in[19 + off];
    const float* dw2 = (const float*)d_in[20 + off];
    const float* db2 = (const float*)d_in[21 + off];
    const float* dlg = (const float*)d_in[22 + off];
    const float* dlb = (const float*)d_in[23 + off];
    const float* ptrw = (const float*)d_in[24 + off];
    const float* ptrb = (const float*)d_in[25 + off];
    const float* fw  = (const float*)d_in[26 + off];
    const float* fb  = (const float*)d_in[27 + off];
    float* out = (float*)d_out;

    float *pe_, *xe_, *q_, *k_, *v_, *t_, *cs_, *ffn_, *xd_, *emb_, *o1_, *o2_, *do_, *pg_, *am_;
    uint2 *wp_, *pa0_, *pa1_, *pa2_;
    cudaGetSymbolAddress((void**)&pe_,  g_pe);
    cudaGetSymbolAddress((void**)&xe_,  g_xe);
    cudaGetSymbolAddress((void**)&q_,   g_q);
    cudaGetSymbolAddress((void**)&k_,   g_k);
    cudaGetSymbolAddress((void**)&v_,   g_v);
    cudaGetSymbolAddress((void**)&t_,   g_t);
    cudaGetSymbolAddress((void**)&cs_,  g_cs);
    cudaGetSymbolAddress((void**)&ffn_, g_ffn);
    cudaGetSymbolAddress((void**)&xd_,  g_xd);
    cudaGetSymbolAddress((void**)&emb_, g_emb);
    cudaGetSymbolAddress((void**)&o1_,  g_o1);
    cudaGetSymbolAddress((void**)&o2_,  g_o2);
    cudaGetSymbolAddress((void**)&do_,  g_do);
    cudaGetSymbolAddress((void**)&pg_,  g_pg);
    cudaGetSymbolAddress((void**)&am_,  g_am);
    cudaGetSymbolAddress((void**)&wp_,  g_wp);
    cudaGetSymbolAddress((void**)&pa0_, g_pa0);
    cudaGetSymbolAddress((void**)&pa1_, g_pa1);
    cudaGetSymbolAddress((void**)&pa2_, g_pa2);

    cudaFuncSetAttribute(fused_attn_kernel, cudaFuncAttributeMaxDynamicSharedMemorySize, ATTN_SMEM_BYTES);
    cudaFuncSetAttribute(gemm_bf16_kernel, cudaFuncAttributeMaxDynamicSharedMemorySize, GEMM_SMEM_BYTES);

    const size_t o_eaw = 0;
    const size_t o_ew1 = o_eaw + 8 * (size_t)SZ_DD;
    const size_t o_ew2 = o_ew1 + 2 * (size_t)SZ_DFF;
    const size_t o_daw = o_ew2 + 2 * (size_t)SZ_DFF;
    const size_t o_dw1 = o_daw + 8 * (size_t)SZ_DD;
    const size_t o_dw2 = o_dw1 + (size_t)SZ_DFF;
    const size_t o_fw  = o_dw2 + (size_t)SZ_DFF;

    auto packB = [&](const float* W, uint2* dst, int K, int N) {
        int n = (K / 2) * N;
        pack_b_kernel<<<(n + 255) / 256, 256>>>(W, dst, K / 2, N);
    };
    auto packA = [&](const float* A, uint2* dst, int M, int K) {
        int n = M * K / 2;
        pack_a_kernel<<<(n + 255) / 256, 256>>>(A, dst, n);
    };
    auto gemm = [&](const uint2* Ap, const uint2* Wp, const float* bias, float* C,
                    int M, int N, int K, int ldc, int relu, const float* rs) {
        dim3 grid(N / 256, M / 64);
        gemm_bf16_kernel<<<grid, 512, GEMM_SMEM_BYTES>>>(Ap, Wp, bias, C, M, N, K, ldc, relu, rs);
    };
    auto attn = [&](const float* Q, const float* Kt, const float* V, float* O,
                    int Sq, int Sk, const float* mask, int mode, float* Pout) {
        dim3 grid((Sq + 31) / 32, kB * kH);
        fused_attn_kernel<<<grid, 256, ATTN_SMEM_BYTES>>>(Q, Kt, V, O, Sq, Sk, mask, mode, Pout);
    };

    const size_t DD2 = (size_t)kD * kD;

    // -------- pack all weights --------
    for (int i = 0; i < 2; ++i)
        for (int j = 0; j < 4; ++j)
            packB(eaw + ((size_t)i * 4 + j) * DD2, wp_ + o_eaw + ((size_t)i * 4 + j) * SZ_DD, kD, kD);
    for (int i = 0; i < 2; ++i) {
        packB(ew1 + (size_t)i * kD * kDFF, wp_ + o_ew1 + (size_t)i * SZ_DFF, kD, kDFF);
        packB(ew2 + (size_t)i * kDFF * kD, wp_ + o_ew2 + (size_t)i * SZ_DFF, kDFF, kD);
    }
    for (int j = 0; j < 8; ++j)
        packB(daw + ((size_t)8 + j) * DD2, wp_ + o_daw + (size_t)j * SZ_DD, kD, kD);
    packB(dw1 + (size_t)1 * kD * kDFF, wp_ + o_dw1, kD, kDFF);
    packB(dw2 + (size_t)1 * kDFF * kD, wp_ + o_dw2, kDFF, kD);
    packB(fw, wp_ + o_fw, kD, kV);

    pe_kernel<<<(kLIN * kD + 255) / 256, 256>>>(pe_);
    embed_enc_kernel<<<(ME * kD + 255) / 256, 256>>>(inp, emb_enc, pe_, xe_);

    // ================= encoder =================
    for (int i = 0; i < 2; ++i) {
        const uint2* w = wp_ + o_eaw + (size_t)i * 4 * SZ_DD;
        const float* b = eab + (size_t)i * 4 * kD;
        packA(xe_, pa0_, ME, kD);
        gemm(pa0_, w + 0 * SZ_DD, b + 0 * kD, q_, ME, kD, kD, kD, 0, nullptr);
        gemm(pa0_, w + 1 * SZ_DD, b + 1 * kD, k_, ME, kD, kD, kD, 0, nullptr);
        gemm(pa0_, w + 2 * SZ_DD, b + 2 * kD, v_, ME, kD, kD, kD, 0, nullptr);
        attn(q_, k_, v_, t_, kLIN, kLIN, enc_mask, 0, nullptr);
        packA(t_, pa0_, ME, kD);
        gemm(pa0_, w + 3 * SZ_DD, b + 3 * kD, q_, ME, kD, kD, kD, 0, nullptr);
        add_ln_kernel<<<ME, 128>>>(xe_, q_, xe_, elg + (i * 2 + 0) * kD, elb + (i * 2 + 0) * kD);
        packA(xe_, pa0_, ME, kD);
        gemm(pa0_, wp_ + o_ew1 + (size_t)i * SZ_DFF, eb1 + (size_t)i * kDFF, ffn_, ME, kDFF, kD, kDFF, 1, nullptr);
        packA(ffn_, pa1_, ME, kDFF);
        gemm(pa1_, wp_ + o_ew2 + (size_t)i * SZ_DFF, eb2 + (size_t)i * kD, q_, ME, kD, kDFF, kD, 0, nullptr);
        add_ln_kernel<<<ME, 128>>>(xe_, q_, xe_, elg + (i * 2 + 1) * kD, elb + (i * 2 + 1) * kD);
    }

    // ================= decoder (only layer 1 live; xd never updated in ref) ========
    embed_dec_kernel<<<(MD * kD + 255) / 256, 256>>>(tar, emb_dec, pe_, xd_, emb_);
    {
        const uint2* w0 = wp_ + o_daw;
        const uint2* w1 = wp_ + o_daw + 4 * (size_t)SZ_DD;
        const float* b0 = dab + (size_t)(1 * 2 + 0) * 4 * kD;
        const float* b1 = dab + (size_t)(1 * 2 + 1) * 4 * kD;
        packA(xd_, pa2_, MD, kD);
        gemm(pa2_, w0 + 0 * SZ_DD, b0 + 0 * kD, q_, MD, kD, kD, kD, 0, nullptr);
        gemm(pa2_, w0 + 1 * SZ_DD, b0 + 1 * kD, k_, MD, kD, kD, kD, 0, nullptr);
        gemm(pa2_, w0 + 2 * SZ_DD, b0 + 2 * kD, v_, MD, kD, kD, kD, 0, nullptr);
        attn(q_, k_, v_, t_, kT, kT, la_mask, 1, nullptr);
        packA(t_, pa2_, MD, kD);
        gemm(pa2_, w0 + 3 * SZ_DD, b0 + 3 * kD, q_, MD, kD, kD, kD, 0, nullptr);
        add_ln_kernel<<<MD, 128>>>(xd_, q_, o1_, dlg + (1 * 3 + 0) * kD, dlb + (1 * 3 + 0) * kD);
        // cross attention
        packA(o1_, pa2_, MD, kD);
        gemm(pa2_, w1 + 0 * SZ_DD, b1 + 0 * kD, q_, MD, kD, kD, kD, 0, nullptr);
        packA(xe_, pa0_, ME, kD);
        gemm(pa0_, w1 + 1 * SZ_DD, b1 + 1 * kD, k_, ME, kD, kD, kD, 0, nullptr);
        gemm(pa0_, w1 + 2 * SZ_DD, b1 + 2 * kD, v_, ME, kD, kD, kD, 0, nullptr);
        attn(q_, k_, v_, t_, kT, kLIN, dec_mask, 0, cs_);
        packA(t_, pa2_, MD, kD);
        gemm(pa2_, w1 + 3 * SZ_DD, b1 + 3 * kD, q_, MD, kD, kD, kD, 0, nullptr);
        add_ln_kernel<<<MD, 128>>>(o1_, q_, o2_, dlg + (1 * 3 + 1) * kD, dlb + (1 * 3 + 1) * kD);
        // ffn
        packA(o2_, pa2_, MD, kD);
        gemm(pa2_, wp_ + o_dw1, db1 + (size_t)1 * kDFF, ffn_, MD, kDFF, kD, kDFF, 1, nullptr);
        packA(ffn_, pa1_, MD, kDFF);
        gemm(pa1_, wp_ + o_dw2, db2 + (size_t)1 * kD, q_, MD, kD, kDFF, kD, 0, nullptr);
        add_ln_kernel<<<MD, 128>>>(o2_, q_, do_, dlg + (1 * 3 + 2) * kD, dlb + (1 * 3 + 2) * kD);
    }

    // ================= pointer-generator head =================
    attn_out_kernel<<<dim3((kT + 31) / 32, kB * kH), 256>>>(cs_, xe_, t_, kT, kLIN);
    pgen_kernel<<<MD, 128>>>(t_, do_, emb_, ptrw, ptrb, pg_);
    packA(do_, pa2_, MD, kD);
    gemm(pa2_, wp_ + o_fw, fb, out, MD, kV, kD, kVE, 0, pg_);
    zero_ext_kernel<<<(MD * kOOV + 255) / 256, 256>>>(out);
    attn_mean_kernel<<<(MD * kLIN + 255) / 256, 256>>>(cs_, am_);
    if (out_size >= MD * kVE + MD * kLIN)
        cudaMemcpyAsync(out + (size_t)MD * kVE, am_,
                        sizeof(float) * MD * kLIN, cudaMemcpyDeviceToDevice, 0);
    scatter_kernel<<<(MD * kLIN + 255) / 256, 256>>>(out, am_, pg_, ext);
}

// round 10
// speedup vs baseline: 1.1872x; 1.1872x over previous
#include <cuda_runtime.h>
#include <cuda_bf16.h>
#include <math.h>
#include <stdint.h>

// ---------------- problem constants ----------------
#define kB    16
#define kLIN  400
#define kT    100
#define kD    512
#define kH    8
#define kDep  64
#define kDFF  2048
#define kV    32000
#define kOOV  100
#define kVE   (kV + kOOV)   // 32100

#define ME (kB * kLIN)      // 6400
#define MD (kB * kT)        // 1600

// packed-weight sizes (uint2 units = 2 elements each)
#define SZ_DD   (kD * kD / 2)
#define SZ_DFF  (kD * kDFF / 2)
#define SZ_FW   (kD * kV / 2)
#define WP_TOTAL (16 * SZ_DD + 6 * SZ_DFF + SZ_FW)

// ---------------- scratch (device globals; no runtime alloc) ----------------
__device__ float g_pe [kLIN * kD];
__device__ float g_xe [ME * kD];
__device__ float g_q  [ME * kD];
__device__ float g_k  [ME * kD];
__device__ float g_v  [ME * kD];
__device__ float g_t  [ME * kD];
__device__ float g_cs [kB * kH * kT * kLIN];   // cross probs (block2)
__device__ float g_xd [MD * kD];
__device__ float g_emb[MD * kD];
__device__ float g_o1 [MD * kD];
__device__ float g_o2 [MD * kD];
__device__ float g_do [MD * kD];
__device__ float g_pg [MD];
__device__ float g_am [MD * kLIN];
__device__ uint2 g_wp [WP_TOTAL];
__device__ uint2 g_pa0[ME * kD / 2];       // packed residual stream (x)
__device__ uint2 g_paT[ME * kD / 2];       // packed attention output
__device__ uint2 g_pa1[ME * kDFF / 2];     // packed ffn hidden
__device__ uint2 g_pa2[MD * kD / 2];       // packed decoder stream

// ---------------- helpers ----------------
__device__ __forceinline__ float warp_sum(float v) {
    #pragma unroll
    for (int o = 16; o > 0; o >>= 1) v += __shfl_xor_sync(0xffffffffu, v, o);
    return v;
}
__device__ __forceinline__ float warp_max(float v) {
    #pragma unroll
    for (int o = 16; o > 0; o >>= 1) v = fmaxf(v, __shfl_xor_sync(0xffffffffu, v, o));
    return v;
}
__device__ __forceinline__ uint2 bfsplit2(float f0, float f1) {
    uint32_t hi;
    asm("cvt.rn.bf16x2.f32 %0, %1, %2;" : "=r"(hi) : "f"(f1), "f"(f0));
    __nv_bfloat162 h = *reinterpret_cast<__nv_bfloat162*>(&hi);
    float r0 = f0 - __bfloat162float(h.x);
    float r1 = f1 - __bfloat162float(h.y);
    uint32_t lo;
    asm("cvt.rn.bf16x2.f32 %0, %1, %2;" : "=r"(lo) : "f"(r1), "f"(r0));
    return make_uint2(hi, lo);
}
__device__ __forceinline__ void mma_bf16(float (&d)[4], const uint32_t (&a)[4], const uint32_t (&b)[2]) {
    asm volatile(
        "mma.sync.aligned.m16n8k16.row.col.f32.bf16.bf16.f32 "
        "{%0,%1,%2,%3},{%4,%5,%6,%7},{%8,%9},{%0,%1,%2,%3};"
        : "+f"(d[0]), "+f"(d[1]), "+f"(d[2]), "+f"(d[3])
        : "r"(a[0]), "r"(a[1]), "r"(a[2]), "r"(a[3]), "r"(b[0]), "r"(b[1]));
}

// ---------------- weight pack (one-time) ----------------
__global__ void pack_b_kernel(const float* __restrict__ in, uint2* __restrict__ out, int Kp, int N) {
    int i = blockIdx.x * 256 + threadIdx.x;
    if (i >= Kp * N) return;
    int kp = i / N, n = i - kp * N;
    float f0 = in[(size_t)(2 * kp) * N + n];
    float f1 = in[(size_t)(2 * kp + 1) * N + n];
    out[i] = bfsplit2(f0, f1);
}

// ---------------- positional encoding ----------------
__global__ void pe_kernel(float* __restrict__ pe) {
    int i = blockIdx.x * 256 + threadIdx.x;
    if (i >= kLIN * kD) return;
    int pos = i / kD, d = i % kD;
    double rate = exp(-(double)(2 * (d / 2)) / (double)kD * log(10000.0));
    double ang  = (double)pos * rate;
    pe[i] = (float)((d & 1) ? cos(ang) : sin(ang));
}

// ---------------- embeddings (emit float + packed) ----------------
__global__ void embed_enc_kernel(const int* __restrict__ idx, const float* __restrict__ emb,
                                 const float* __restrict__ pe, float* __restrict__ x,
                                 uint2* __restrict__ xpk) {
    int i = blockIdx.x * 256 + threadIdx.x;        // pair index
    if (i >= ME * kD / 2) return;
    int dp = i & 255;                               // kD/2 = 256 pairs per row
    int bs = i >> 8;
    int s  = bs % kLIN;
    int d  = dp << 1;
    float2 e = *(const float2*)&emb[(size_t)idx[bs] * kD + d];
    float2 p = *(const float2*)&pe[s * kD + d];
    float scale = sqrtf((float)kD);
    float x0 = e.x * scale + p.x, x1 = e.y * scale + p.y;
    *(float2*)&x[(size_t)bs * kD + d] = make_float2(x0, x1);
    xpk[i] = bfsplit2(x0, x1);
}
__global__ void embed_dec_kernel(const int* __restrict__ idx, const float* __restrict__ emb,
                                 const float* __restrict__ pe, float* __restrict__ x,
                                 uint2* __restrict__ xpk, float* __restrict__ eraw) {
    int i = blockIdx.x * 256 + threadIdx.x;
    if (i >= MD * kD / 2) return;
    int dp = i & 255;
    int bs = i >> 8;
    int s  = bs % kT;
    int d  = dp << 1;
    float2 e = *(const float2*)&emb[(size_t)idx[bs] * kD + d];
    float2 p = *(const float2*)&pe[s * kD + d];
    *(float2*)&eraw[(size_t)bs * kD + d] = e;
    float scale = sqrtf((float)kD);
    float x0 = e.x * scale + p.x, x1 = e.y * scale + p.y;
    *(float2*)&x[(size_t)bs * kD + d] = make_float2(x0, x1);
    xpk[i] = bfsplit2(x0, x1);
}

// ---------------- bf16 3-term tensor-core GEMM (R8 structure) ----------------
// C[M,N] = A[M,K] @ W[K,N] + bias (+relu, +row-scale | packout). Pre-packed hi/lo.
// Tile 64x128, BK=32 (16 kpairs), 256 threads = 8 warps (2M x 4N), warp 32x32.
// packout: C is uint2*, writes bf16 hi/lo pairs (ldc in elements).
__global__ void __launch_bounds__(256)
gemm_bf16_kernel(const uint2* __restrict__ Ap, const uint2* __restrict__ Wp,
                 const float* __restrict__ bias, float* __restrict__ C,
                 int M, int N, int K, int ldc, int relu, const float* __restrict__ rs,
                 int packout) {
    __shared__ uint2 As[16][68];
    __shared__ uint2 Bs[16][132];

    const int t = threadIdx.x, lane = t & 31, wid = t >> 5;
    const int wm = wid & 1, wn = wid >> 1;
    const int g = lane >> 2, c = lane & 3;
    const int bm = blockIdx.y << 6, bn = blockIdx.x << 7;
    const int a_row = t & 63, a_kq = (t >> 6) << 2;
    const int b_kp = t >> 4, b_n = (t & 15) << 1;
    const int Kp = K >> 1;

    const uint2* aptr = Ap + (size_t)(bm + a_row) * Kp + a_kq;
    float acc[2][4][4] = {};

    for (int kp0 = 0; kp0 < Kp; kp0 += 16) {
        uint4 av0 = *(const uint4*)(aptr + kp0);
        uint4 av1 = *(const uint4*)(aptr + kp0 + 2);
        const uint2* wrow = Wp + (size_t)(kp0 + b_kp) * N + bn + b_n;
        uint4 bv0 = *(const uint4*)(wrow);
        uint4 bv1 = *(const uint4*)(wrow + 32);
        uint4 bv2 = *(const uint4*)(wrow + 64);
        uint4 bv3 = *(const uint4*)(wrow + 96);
        __syncthreads();
        As[a_kq + 0][a_row] = make_uint2(av0.x, av0.y);
        As[a_kq + 1][a_row] = make_uint2(av0.z, av0.w);
        As[a_kq + 2][a_row] = make_uint2(av1.x, av1.y);
        As[a_kq + 3][a_row] = make_uint2(av1.z, av1.w);
        *(uint4*)&Bs[b_kp][b_n]      = bv0;
        *(uint4*)&Bs[b_kp][b_n + 32] = bv1;
        *(uint4*)&Bs[b_kp][b_n + 64] = bv2;
        *(uint4*)&Bs[b_kp][b_n + 96] = bv3;
        __syncthreads();
        #pragma unroll
        for (int s = 0; s < 2; ++s) {
            const int sb = s << 3;
            uint2 af[2][4], bf[4][2];
            #pragma unroll
            for (int mi = 0; mi < 2; ++mi) {
                int m = (wm << 5) + (mi << 4) + g;
                af[mi][0] = As[sb + c][m];
                af[mi][1] = As[sb + c][m + 8];
                af[mi][2] = As[sb + c + 4][m];
                af[mi][3] = As[sb + c + 4][m + 8];
            }
            #pragma unroll
            for (int ni = 0; ni < 4; ++ni) {
                int n = (wn << 5) + (ni << 3) + g;
                bf[ni][0] = Bs[sb + c][n];
                bf[ni][1] = Bs[sb + c + 4][n];
            }
            #pragma unroll
            for (int mi = 0; mi < 2; ++mi) {
                uint32_t ah[4] = {af[mi][0].x, af[mi][1].x, af[mi][2].x, af[mi][3].x};
                uint32_t al[4] = {af[mi][0].y, af[mi][1].y, af[mi][2].y, af[mi][3].y};
                #pragma unroll
                for (int ni = 0; ni < 4; ++ni) {
                    uint32_t bh[2] = {bf[ni][0].x, bf[ni][1].x};
                    uint32_t bl[2] = {bf[ni][0].y, bf[ni][1].y};
                    mma_bf16(acc[mi][ni], al, bh);
                    mma_bf16(acc[mi][ni], ah, bl);
                    mma_bf16(acc[mi][ni], ah, bh);
                }
            }
        }
    }

    // ---- epilogue ----
    #pragma unroll
    for (int mi = 0; mi < 2; ++mi) {
        int r0 = bm + (wm << 5) + (mi << 4) + g;
        float s0 = rs ? rs[r0] : 1.0f;
        float s1 = rs ? rs[r0 + 8] : 1.0f;
        #pragma unroll
        for (int ni = 0; ni < 4; ++ni) {
            int c0 = bn + (wn << 5) + (ni << 3) + (c << 1);
            float bb0 = bias[c0], bb1 = bias[c0 + 1];
            float v0 = acc[mi][ni][0] + bb0, v1 = acc[mi][ni][1] + bb1;
            float v2 = acc[mi][ni][2] + bb0, v3 = acc[mi][ni][3] + bb1;
            if (relu) {
                v0 = fmaxf(v0, 0.0f); v1 = fmaxf(v1, 0.0f);
                v2 = fmaxf(v2, 0.0f); v3 = fmaxf(v3, 0.0f);
            }
            if (packout) {
                uint2* Cp = (uint2*)C;
                int ldp = ldc >> 1;
                Cp[(size_t)r0 * ldp + (c0 >> 1)]       = bfsplit2(v0 * s0, v1 * s0);
                Cp[(size_t)(r0 + 8) * ldp + (c0 >> 1)] = bfsplit2(v2 * s1, v3 * s1);
            } else {
                *(float2*)&C[(size_t)r0 * ldc + c0]       = make_float2(v0 * s0, v1 * s0);
                *(float2*)&C[(size_t)(r0 + 8) * ldc + c0] = make_float2(v2 * s1, v3 * s1);
            }
        }
    }
}

// ---------------- fused attention: scores -> softmax -> P@V, packed output ------
#define ATTN_SMEM_BYTES ((32*408 + 32*68 + 32*68) * 4)
__global__ void __launch_bounds__(256)
fused_attn_kernel(const float* __restrict__ Q, const float* __restrict__ Kt,
                  const float* __restrict__ V, uint2* __restrict__ Opk,
                  int Sq, int Sk, const float* __restrict__ mask, int mode,
                  float* __restrict__ Pout) {
    extern __shared__ float sm_f[];
    float (*Ss)[408] = (float(*)[408])sm_f;
    float (*Qs)[68]  = (float(*)[68])(sm_f + 32 * 408);
    float (*Ks)[68]  = (float(*)[68])(sm_f + 32 * 408 + 32 * 68);

    const int tid = threadIdx.x;
    const int bh = blockIdx.y, b = bh >> 3, h = bh & 7;
    const int q0 = blockIdx.x * 32;

    for (int i = tid; i < 32 * 16; i += 256) {
        int r = i >> 4, c4 = (i & 15) << 2;
        float4 qv = make_float4(0, 0, 0, 0);
        if (q0 + r < Sq) qv = *(const float4*)&Q[((size_t)(b * Sq + q0 + r)) * kD + h * kDep + c4];
        *(float4*)&Qs[r][c4] = qv;
    }

    const int tx = tid & 15, ty = tid >> 4;
    for (int k0 = 0; k0 < Sk; k0 += 32) {
        for (int i = tid; i < 32 * 16; i += 256) {
            int r = i >> 4, c4 = (i & 15) << 2;
            float4 kv = make_float4(0, 0, 0, 0);
            if (k0 + r < Sk) kv = *(const float4*)&Kt[((size_t)(b * Sk + k0 + r)) * kD + h * kDep + c4];
            *(float4*)&Ks[r][c4] = kv;
        }
        __syncthreads();
        float acc[2][2] = {};
        #pragma unroll
        for (int d4 = 0; d4 < kDep; d4 += 4) {
            float4 a0 = *(const float4*)&Qs[ty * 2 + 0][d4];
            float4 a1 = *(const float4*)&Qs[ty * 2 + 1][d4];
            float4 b0 = *(const float4*)&Ks[tx * 2 + 0][d4];
            float4 b1 = *(const float4*)&Ks[tx * 2 + 1][d4];
            acc[0][0] += a0.x*b0.x + a0.y*b0.y + a0.z*b0.z + a0.w*b0.w;
            acc[0][1] += a0.x*b1.x + a0.y*b1.y + a0.z*b1.z + a0.w*b1.w;
            acc[1][0] += a1.x*b0.x + a1.y*b0.y + a1.z*b0.z + a1.w*b0.w;
            acc[1][1] += a1.x*b1.x + a1.y*b1.y + a1.z*b1.z + a1.w*b1.w;
        }
        #pragma unroll
        for (int i = 0; i < 2; ++i) {
            int qg = q0 + ty * 2 + i;
            #pragma unroll
            for (int j = 0; j < 2; ++j) {
                int kg = k0 + tx * 2 + j;
                if (qg < Sq && kg < Sk) {
                    float vv = acc[i][j] * 0.125f;
                    float mk = (mode == 0) ? mask[(size_t)b * Sk + kg]
                                           : mask[((size_t)b * Sq + qg) * Sk + kg];
                    Ss[ty * 2 + i][kg] = vv + mk * (-1e9f);
                }
            }
        }
        __syncthreads();
    }

    {
        const int wid = tid >> 5, lane = tid & 31;
        #pragma unroll
        for (int rr = 0; rr < 4; ++rr) {
            int r = (wid << 2) + rr;
            if (q0 + r < Sq) {
                float m = -1e30f;
                for (int i = lane; i < Sk; i += 32) m = fmaxf(m, Ss[r][i]);
                m = warp_max(m);
                float s = 0.0f;
                for (int i = lane; i < Sk; i += 32) { float e = __expf(Ss[r][i] - m); Ss[r][i] = e; s += e; }
                s = warp_sum(s);
                float inv = 1.0f / s;
                for (int i = lane; i < Sk; i += 32) Ss[r][i] *= inv;
            }
        }
    }
    __syncthreads();

    if (Pout) {
        for (int idx = tid; idx < 32 * Sk; idx += 256) {
            int r = idx / Sk, col = idx - r * Sk;
            if (q0 + r < Sq)
                Pout[((size_t)bh * Sq + q0 + r) * Sk + col] = Ss[r][col];
        }
    }

    const int dcol = tid & 63, qb = tid >> 6;
    float acc[8] = {};
    for (int k0 = 0; k0 < Sk; k0 += 32) {
        for (int i = tid; i < 32 * 16; i += 256) {
            int r = i >> 4, c4 = (i & 15) << 2;
            float4 v4 = make_float4(0, 0, 0, 0);
            if (k0 + r < Sk) v4 = *(const float4*)&V[((size_t)(b * Sk + k0 + r)) * kD + h * kDep + c4];
            *(float4*)&Ks[r][c4] = v4;
        }
        __syncthreads();
        int klim = Sk - k0; if (klim > 32) klim = 32;
        for (int kk = 0; kk < klim; ++kk) {
            float vv = Ks[kk][dcol];
            #pragma unroll
            for (int j = 0; j < 8; ++j)
                acc[j] = fmaf(Ss[qb + (j << 2)][k0 + kk], vv, acc[j]);
        }
        __syncthreads();
    }
    // packed output: lanes pair up adjacent d-columns via shfl
    #pragma unroll
    for (int j = 0; j < 8; ++j) {
        float other = __shfl_xor_sync(0xffffffffu, acc[j], 1);
        int qg = q0 + qb + (j << 2);
        if (((dcol & 1) == 0) && qg < Sq) {
            Opk[((size_t)(b * Sq + qg)) * (kD / 2) + ((h * kDep + dcol) >> 1)] =
                bfsplit2(acc[j], other);
        }
    }
}

// ---------------- context einsum: O = P @ V (float, pointer head only) ----------
__global__ void __launch_bounds__(256)
attn_out_kernel(const float* __restrict__ P, const float* __restrict__ V,
                float* __restrict__ O, int Sq, int Sk) {
    __shared__ float Ps[32][33];
    __shared__ float Vs[32][64];
    int tid = threadIdx.x;
    int bh = blockIdx.y, b = bh >> 3, h = bh & 7;
    int q0 = blockIdx.x * 32;
    const float* p = P + (size_t)bh * Sq * Sk;
    int dcol = tid & 63, qb = tid >> 6;
    float acc[8] = {};
    for (int k0 = 0; k0 < Sk; k0 += 32) {
        {
            int r = tid >> 3, cc = (tid & 7) << 2;
            int qg = q0 + r, kg = k0 + cc;
            float4 v4 = make_float4(0, 0, 0, 0);
            if (qg < Sq && kg < Sk)
                v4 = *(const float4*)&p[(size_t)qg * Sk + kg];
            Ps[r][cc] = v4.x; Ps[r][cc + 1] = v4.y; Ps[r][cc + 2] = v4.z; Ps[r][cc + 3] = v4.w;
        }
        for (int i = tid; i < 32 * 16; i += 256) {
            int r = i >> 4, c4 = (i & 15) << 2;
            int kg = k0 + r;
            float4 v4 = make_float4(0, 0, 0, 0);
            if (kg < Sk) v4 = *(const float4*)&V[((size_t)(b * Sk + kg)) * kD + h * kDep + c4];
            *(float4*)&Vs[r][c4] = v4;
        }
        __syncthreads();
        #pragma unroll
        for (int kk = 0; kk < 32; ++kk) {
            float vv = Vs[kk][dcol];
            #pragma unroll
            for (int j = 0; j < 8; ++j)
                acc[j] = fmaf(Ps[qb + (j << 2)][kk], vv, acc[j]);
        }
        __syncthreads();
    }
    #pragma unroll
    for (int j = 0; j < 8; ++j) {
        int qg = q0 + qb + (j << 2);
        if (qg < Sq) O[((size_t)(b * Sq + qg)) * kD + h * kDep + dcol] = acc[j];
    }
}

// ---------------- y = LN(x + a) * g + b, emits float + packed ----------------
__global__ void add_ln_kernel(const float* __restrict__ x, const float* __restrict__ a,
                              float* __restrict__ y, uint2* __restrict__ ypk,
                              const float* __restrict__ g, const float* __restrict__ bb) {
    int row = blockIdx.x, tid = threadIdx.x;   // 128 threads, 4 consecutive d each
    size_t base = (size_t)row * kD;
    int d0 = tid << 2;
    float4 xv = *(const float4*)&x[base + d0];
    float4 av = *(const float4*)&a[base + d0];
    float v0 = xv.x + av.x, v1 = xv.y + av.y, v2 = xv.z + av.z, v3 = xv.w + av.w;
    float s = v0 + v1 + v2 + v3;
    float s2 = v0*v0 + v1*v1 + v2*v2 + v3*v3;
    __shared__ float shs[4], shs2[4];
    s = warp_sum(s); s2 = warp_sum(s2);
    if ((tid & 31) == 0) { shs[tid >> 5] = s; shs2[tid >> 5] = s2; }
    __syncthreads();
    float S = shs[0] + shs[1] + shs[2] + shs[3];
    float S2 = shs2[0] + shs2[1] + shs2[2] + shs2[3];
    float mu = S * (1.0f / kD);
    float var = S2 * (1.0f / kD) - mu * mu;
    float rstd = rsqrtf(var + 1e-6f);
    float4 gv = *(const float4*)&g[d0];
    float4 bv = *(const float4*)&bb[d0];
    float y0 = (v0 - mu) * rstd * gv.x + bv.x;
    float y1 = (v1 - mu) * rstd * gv.y + bv.y;
    float y2 = (v2 - mu) * rstd * gv.z + bv.z;
    float y3 = (v3 - mu) * rstd * gv.w + bv.w;
    *(float4*)&y[base + d0] = make_float4(y0, y1, y2, y3);
    uint2 p0 = bfsplit2(y0, y1), p1 = bfsplit2(y2, y3);
    *(uint4*)&ypk[(size_t)row * (kD / 2) + (tid << 1)] = make_uint4(p0.x, p0.y, p1.x, p1.y);
}

// ---------------- p_gen ----------------
__global__ void pgen_kernel(const float* __restrict__ ctx, const float* __restrict__ dec,
                            const float* __restrict__ emb, const float* __restrict__ w,
                            const float* __restrict__ bvec, float* __restrict__ pg) {
    int row = blockIdx.x, tid = threadIdx.x;
    float s = 0.0f;
    for (int d = tid; d < kD; d += 128) {
        size_t o = (size_t)row * kD + d;
        s += ctx[o] * w[d] + dec[o] * w[kD + d] + emb[o] * w[2 * kD + d];
    }
    __shared__ float sh[4];
    s = warp_sum(s);
    if ((tid & 31) == 0) sh[tid >> 5] = s;
    __syncthreads();
    if (tid == 0) {
        float t = sh[0] + sh[1] + sh[2] + sh[3] + bvec[0] + bvec[1] + bvec[2];
        pg[row] = 1.0f / (1.0f + expf(-t));
    }
}

// ---------------- attn_mean ----------------
__global__ void attn_mean_kernel(const float* __restrict__ P, float* __restrict__ am) {
    int i = blockIdx.x * 256 + threadIdx.x;
    if (i >= MD * kLIN) return;
    int l = i % kLIN;
    int bt = i / kLIN;
    int b = bt / kT, t = bt % kT;
    float s = 0.0f;
    #pragma unroll
    for (int h = 0; h < kH; ++h)
        s += P[(((size_t)(b * kH + h) * kT) + t) * kLIN + l];
    am[i] = s * (1.0f / kH);
}

// ---------------- zero extension columns ----------------
__global__ void zero_ext_kernel(float* __restrict__ out) {
    int i = blockIdx.x * 256 + threadIdx.x;
    if (i >= MD * kOOV) return;
    int row = i / kOOV, c = i % kOOV;
    out[(size_t)row * kVE + kV + c] = 0.0f;
}

// ---------------- copy scatter ----------------
__global__ void scatter_kernel(float* __restrict__ out, const float* __restrict__ am,
                               const float* __restrict__ pg, const int* __restrict__ ext) {
    int i = blockIdx.x * 256 + threadIdx.x;
    if (i >= MD * kLIN) return;
    int l = i % kLIN;
    int bt = i / kLIN;
    int b = bt / kT;
    float v = (1.0f - pg[bt]) * am[i];
    int vi = ext[b * kLIN + l];
    atomicAdd(&out[(size_t)bt * kVE + vi], v);
}

// ---------------- host orchestration ----------------
extern "C" void kernel_launch(void* const* d_in, const int* in_sizes, int n_in,
                              void* d_out, int out_size) {
    int off = (n_in > 6 && in_sizes[6] == 1) ? 1 : 0;
    const int*   inp      = (const int*)d_in[0];
    const int*   tar      = (const int*)d_in[1];
    const int*   ext      = (const int*)d_in[2];
    const float* enc_mask = (const float*)d_in[3];
    const float* la_mask  = (const float*)d_in[4];
    const float* dec_mask = (const float*)d_in[5];
    const float* emb_enc  = (const float*)d_in[6 + off];
    const float* emb_dec  = (const float*)d_in[7 + off];
    const float* eaw = (const float*)d_in[8 + off];
    const float* eab = (const float*)d_in[9 + off];
    const float* ew1 = (const float*)d_in[10 + off];
    const float* eb1 = (const float*)d_in[11 + off];
    const float* ew2 = (const float*)d_in[12 + off];
    const float* eb2 = (const float*)d_in[13 + off];
    const float* elg = (const float*)d_in[14 + off];
    const float* elb = (const float*)d_in[15 + off];
    const float* daw = (const float*)d_in[16 + off];
    const float* dab = (const float*)d_in[17 + off];
    const float* dw1 = (const float*)d_in[18 + off];
    const float* db1 = (const float*)d_in[19 + off];
    const float* dw2 = (const float*)d_in[20 + off];
    const float* db2 = (const float*)d_in[21 + off];
    const float* dlg = (const float*)d_in[22 + off];
    const float* dlb = (const float*)d_in[23 + off];
    const float* ptrw = (const float*)d_in[24 + off];
    const float* ptrb = (const float*)d_in[25 + off];
    const float* fw  = (const float*)d_in[26 + off];
    const float* fb  = (const float*)d_in[27 + off];
    float* out = (float*)d_out;

    float *pe_, *xe_, *q_, *k_, *v_, *t_, *cs_, *xd_, *emb_, *o1_, *o2_, *do_, *pg_, *am_;
    uint2 *wp_, *pa0_, *paT_, *pa1_, *pa2_;
    cudaGetSymbolAddress((void**)&pe_,  g_pe);
    cudaGetSymbolAddress((void**)&xe_,  g_xe);
    cudaGetSymbolAddress((void**)&q_,   g_q);
    cudaGetSymbolAddress((void**)&k_,   g_k);
    cudaGetSymbolAddress((void**)&v_,   g_v);
    cudaGetSymbolAddress((void**)&t_,   g_t);
    cudaGetSymbolAddress((void**)&cs_,  g_cs);
    cudaGetSymbolAddress((void**)&xd_,  g_xd);
    cudaGetSymbolAddress((void**)&emb_, g_emb);
    cudaGetSymbolAddress((void**)&o1_,  g_o1);
    cudaGetSymbolAddress((void**)&o2_,  g_o2);
    cudaGetSymbolAddress((void**)&do_,  g_do);
    cudaGetSymbolAddress((void**)&pg_,  g_pg);
    cudaGetSymbolAddress((void**)&am_,  g_am);
    cudaGetSymbolAddress((void**)&wp_,  g_wp);
    cudaGetSymbolAddress((void**)&pa0_, g_pa0);
    cudaGetSymbolAddress((void**)&paT_, g_paT);
    cudaGetSymbolAddress((void**)&pa1_, g_pa1);
    cudaGetSymbolAddress((void**)&pa2_, g_pa2);

    cudaFuncSetAttribute(fused_attn_kernel, cudaFuncAttributeMaxDynamicSharedMemorySize, ATTN_SMEM_BYTES);

    const size_t o_eaw = 0;
    const size_t o_ew1 = o_eaw + 8 * (size_t)SZ_DD;
    const size_t o_ew2 = o_ew1 + 2 * (size_t)SZ_DFF;
    const size_t o_daw = o_ew2 + 2 * (size_t)SZ_DFF;
    const size_t o_dw1 = o_daw + 8 * (size_t)SZ_DD;
    const size_t o_dw2 = o_dw1 + (size_t)SZ_DFF;
    const size_t o_fw  = o_dw2 + (size_t)SZ_DFF;

    auto packB = [&](const float* W, uint2* dst, int K, int N) {
        int n = (K / 2) * N;
        pack_b_kernel<<<(n + 255) / 256, 256>>>(W, dst, K / 2, N);
    };
    auto gemm = [&](const uint2* Ap, const uint2* Wp, const float* bias, float* C,
                    int M, int N, int K, int ldc, int relu, const float* rs, int packout = 0) {
        dim3 grid(N / 128, M / 64);
        gemm_bf16_kernel<<<grid, 256>>>(Ap, Wp, bias, C, M, N, K, ldc, relu, rs, packout);
    };
    auto attn = [&](const float* Q, const float* Kt, const float* V, uint2* Opk,
                    int Sq, int Sk, const float* mask, int mode, float* Pout) {
        dim3 grid((Sq + 31) / 32, kB * kH);
        fused_attn_kernel<<<grid, 256, ATTN_SMEM_BYTES>>>(Q, Kt, V, Opk, Sq, Sk, mask, mode, Pout);
    };

    const size_t DD2 = (size_t)kD * kD;

    // -------- pack all weights (one-time per launch) --------
    for (int i = 0; i < 2; ++i)
        for (int j = 0; j < 4; ++j)
            packB(eaw + ((size_t)i * 4 + j) * DD2, wp_ + o_eaw + ((size_t)i * 4 + j) * SZ_DD, kD, kD);
    for (int i = 0; i < 2; ++i) {
        packB(ew1 + (size_t)i * kD * kDFF, wp_ + o_ew1 + (size_t)i * SZ_DFF, kD, kDFF);
        packB(ew2 + (size_t)i * kDFF * kD, wp_ + o_ew2 + (size_t)i * SZ_DFF, kDFF, kD);
    }
    for (int j = 0; j < 8; ++j)
        packB(daw + ((size_t)8 + j) * DD2, wp_ + o_daw + (size_t)j * SZ_DD, kD, kD);
    packB(dw1 + (size_t)1 * kD * kDFF, wp_ + o_dw1, kD, kDFF);
    packB(dw2 + (size_t)1 * kDFF * kD, wp_ + o_dw2, kDFF, kD);
    packB(fw, wp_ + o_fw, kD, kV);

    pe_kernel<<<(kLIN * kD + 255) / 256, 256>>>(pe_);
    embed_enc_kernel<<<(ME * kD / 2 + 255) / 256, 256>>>(inp, emb_enc, pe_, xe_, pa0_);

    // ================= encoder =================
    for (int i = 0; i < 2; ++i) {
        const uint2* w = wp_ + o_eaw + (size_t)i * 4 * SZ_DD;
        const float* b = eab + (size_t)i * 4 * kD;
        gemm(pa0_, w + 0 * SZ_DD, b + 0 * kD, q_, ME, kD, kD, kD, 0, nullptr);
        gemm(pa0_, w + 1 * SZ_DD, b + 1 * kD, k_, ME, kD, kD, kD, 0, nullptr);
        gemm(pa0_, w + 2 * SZ_DD, b + 2 * kD, v_, ME, kD, kD, kD, 0, nullptr);
        attn(q_, k_, v_, paT_, kLIN, kLIN, enc_mask, 0, nullptr);
        gemm(paT_, w + 3 * SZ_DD, b + 3 * kD, q_, ME, kD, kD, kD, 0, nullptr);
        add_ln_kernel<<<ME, 128>>>(xe_, q_, xe_, pa0_, elg + (i * 2 + 0) * kD, elb + (i * 2 + 0) * kD);
        gemm(pa0_, wp_ + o_ew1 + (size_t)i * SZ_DFF, eb1 + (size_t)i * kDFF,
             (float*)pa1_, ME, kDFF, kD, kDFF, 1, nullptr, 1);
        gemm(pa1_, wp_ + o_ew2 + (size_t)i * SZ_DFF, eb2 + (size_t)i * kD, q_, ME, kD, kDFF, kD, 0, nullptr);
        add_ln_kernel<<<ME, 128>>>(xe_, q_, xe_, pa0_, elg + (i * 2 + 1) * kD, elb + (i * 2 + 1) * kD);
    }
    // pa0_ now holds the packed final encoder output (for cross K/V)

    // ================= decoder (only layer 1 live; xd never updated in ref) ========
    embed_dec_kernel<<<(MD * kD / 2 + 255) / 256, 256>>>(tar, emb_dec, pe_, xd_, pa2_, emb_);
    {
        const uint2* w0 = wp_ + o_daw;
        const uint2* w1 = wp_ + o_daw + 4 * (size_t)SZ_DD;
        const float* b0 = dab + (size_t)(1 * 2 + 0) * 4 * kD;
        const float* b1 = dab + (size_t)(1 * 2 + 1) * 4 * kD;
        gemm(pa2_, w0 + 0 * SZ_DD, b0 + 0 * kD, q_, MD, kD, kD, kD, 0, nullptr);
        gemm(pa2_, w0 + 1 * SZ_DD, b0 + 1 * kD, k_, MD, kD, kD, kD, 0, nullptr);
        gemm(pa2_, w0 + 2 * SZ_DD, b0 + 2 * kD, v_, MD, kD, kD, kD, 0, nullptr);
        attn(q_, k_, v_, pa2_, kT, kT, la_mask, 1, nullptr);
        gemm(pa2_, w0 + 3 * SZ_DD, b0 + 3 * kD, q_, MD, kD, kD, kD, 0, nullptr);
        add_ln_kernel<<<MD, 128>>>(xd_, q_, o1_, pa2_, dlg + (1 * 3 + 0) * kD, dlb + (1 * 3 + 0) * kD);
        // cross attention
        gemm(pa2_, w1 + 0 * SZ_DD, b1 + 0 * kD, q_, MD, kD, kD, kD, 0, nullptr);
        gemm(pa0_, w1 + 1 * SZ_DD, b1 + 1 * kD, k_, ME, kD, kD, kD, 0, nullptr);
        gemm(pa0_, w1 + 2 * SZ_DD, b1 + 2 * kD, v_, ME, kD, kD, kD, 0, nullptr);
        attn(q_, k_, v_, pa2_, kT, kLIN, dec_mask, 0, cs_);
        gemm(pa2_, w1 + 3 * SZ_DD, b1 + 3 * kD, q_, MD, kD, kD, kD, 0, nullptr);
        add_ln_kernel<<<MD, 128>>>(o1_, q_, o2_, pa2_, dlg + (1 * 3 + 1) * kD, dlb + (1 * 3 + 1) * kD);
        // ffn
        gemm(pa2_, wp_ + o_dw1, db1 + (size_t)1 * kDFF, (float*)pa1_, MD, kDFF, kD, kDFF, 1, nullptr, 1);
        gemm(pa1_, wp_ + o_dw2, db2 + (size_t)1 * kD, q_, MD, kD, kDFF, kD, 0, nullptr);
        add_ln_kernel<<<MD, 128>>>(o2_, q_, do_, pa2_, dlg + (1 * 3 + 2) * kD, dlb + (1 * 3 + 2) * kD);
    }

    // ================= pointer-generator head =================
    attn_out_kernel<<<dim3((kT + 31) / 32, kB * kH), 256>>>(cs_, xe_, t_, kT, kLIN);
    pgen_kernel<<<MD, 128>>>(t_, do_, emb_, ptrw, ptrb, pg_);
    gemm(pa2_, wp_ + o_fw, fb, out, MD, kV, kD, kVE, 0, pg_);
    zero_ext_kernel<<<(MD * kOOV + 255) / 256, 256>>>(out);
    attn_mean_kernel<<<(MD * kLIN + 255) / 256, 256>>>(cs_, am_);
    if (out_size >= MD * kVE + MD * kLIN)
        cudaMemcpyAsync(out + (size_t)MD * kVE, am_,
                        sizeof(float) * MD * kLIN, cudaMemcpyDeviceToDevice, 0);
    scatter_kernel<<<(MD * kLIN + 255) / 256, 256>>>(out, am_, pg_, ext);
}